// round 3
// baseline (speedup 1.0000x reference)
#include <cuda_runtime.h>
#include <cstdint>
#include <cstddef>

#define NTIME 20
#define V     128
#define F     128
#define LRELU_ALPHA 0.2f

#define OUT_HP_ELEMS   (NTIME * V * F)
#define ATT_OFF        OUT_HP_ELEMS

__device__ float g_Wh[NTIME * V * F];
__device__ float g_e1[NTIME * V * F];
__device__ float g_e2[NTIME * V * F];

// ----------------------------------------------------------------------------
// Kernel 1: fused  Wh = h @ W ;  e1 = Wh @ a[:128] ;  e2 = Wh @ a[128:]
// MT=8 rows/block, 256 threads (f = tid&127, half = tid>>7, 4 rows each).
// Inner loops unrolled over k by 4 with LDS.128 row fetches (4 FMA per LDS).
// ----------------------------------------------------------------------------
#define MT 8

__global__ void __launch_bounds__(256) gemm_fused(
    const float* __restrict__ h,
    const float* __restrict__ W,
    const float* __restrict__ a)
{
    __shared__ float hs[MT * F];
    __shared__ float whs[MT * F];

    const int tid  = threadIdx.x;
    const int f    = tid & 127;
    const int half = tid >> 7;
    const int m0   = blockIdx.x * MT;

    ((float4*)hs)[tid] = ((const float4*)(h + (size_t)m0 * F))[tid];
    __syncthreads();

    float acc[4] = {0.f, 0.f, 0.f, 0.f};

#pragma unroll 4
    for (int k4 = 0; k4 < F / 4; k4++) {
        float wv[4];
#pragma unroll
        for (int u = 0; u < 4; u++)
            wv[u] = __ldg(W + (k4 * 4 + u) * F + f);
#pragma unroll
        for (int r = 0; r < 4; r++) {
            const float4 hv = ((const float4*)(hs + (half * 4 + r) * F))[k4];
            acc[r] = fmaf(hv.x, wv[0], acc[r]);
            acc[r] = fmaf(hv.y, wv[1], acc[r]);
            acc[r] = fmaf(hv.z, wv[2], acc[r]);
            acc[r] = fmaf(hv.w, wv[3], acc[r]);
        }
    }

#pragma unroll
    for (int r = 0; r < 4; r++) {
        const int row = half * 4 + r;
        whs[row * F + f] = acc[r];
        g_Wh[(size_t)(m0 + row) * F + f] = acc[r];
    }
    __syncthreads();

    float ac1[4] = {0.f, 0.f, 0.f, 0.f};
    float ac2[4] = {0.f, 0.f, 0.f, 0.f};

#pragma unroll 2
    for (int k4 = 0; k4 < F / 4; k4++) {
        float a1v[4], a2v[4];
#pragma unroll
        for (int u = 0; u < 4; u++) {
            a1v[u] = __ldg(a + (k4 * 4 + u) * F + f);
            a2v[u] = __ldg(a + (F + k4 * 4 + u) * F + f);
        }
#pragma unroll
        for (int r = 0; r < 4; r++) {
            const float4 wv = ((const float4*)(whs + (half * 4 + r) * F))[k4];
            ac1[r] = fmaf(wv.x, a1v[0], ac1[r]);
            ac1[r] = fmaf(wv.y, a1v[1], ac1[r]);
            ac1[r] = fmaf(wv.z, a1v[2], ac1[r]);
            ac1[r] = fmaf(wv.w, a1v[3], ac1[r]);
            ac2[r] = fmaf(wv.x, a2v[0], ac2[r]);
            ac2[r] = fmaf(wv.y, a2v[1], ac2[r]);
            ac2[r] = fmaf(wv.z, a2v[2], ac2[r]);
            ac2[r] = fmaf(wv.w, a2v[3], ac2[r]);
        }
    }

#pragma unroll
    for (int r = 0; r < 4; r++) {
        const int row = half * 4 + r;
        g_e1[(size_t)(m0 + row) * F + f] = ac1[r];
        g_e2[(size_t)(m0 + row) * F + f] = ac2[r];
    }
}

// ----------------------------------------------------------------------------
// Kernel 2: fused leakyrelu + mask + softmax + weighted sum + elu + attn write.
//
// Block = (t, f-half, i-group of 32). 512 threads = 16 warps.
// Warp owns 2 adjacent i's: half-warp (16 lanes) per i, lane covers 4 f's
// (float4) spanning the 64-wide f-half. adj test is half-warp-uniform.
// Grid = 8 x 20 = 160 blocks -> single wave at 2 CTAs/SM.
// smem = 2 * 32KB tiles + 16KB adj = 80KB.
// ----------------------------------------------------------------------------
#define FH  64
#define IPB 32
#define ATTN_SMEM_BYTES ((V * FH * 2 + IPB * V) * (int)sizeof(float))

__global__ void __launch_bounds__(512, 2) attn_fused(
    const float* __restrict__ adj,
    float* __restrict__ out)
{
    extern __shared__ float sm[];
    float* e2s  = sm;                 // [V][FH]
    float* whs  = sm + V * FH;        // [V][FH]
    float* adjs = sm + 2 * V * FH;    // [IPB][V]

    const int t    = blockIdx.y;
    const int bx   = blockIdx.x;      // 0..7
    const int fh   = bx & 1;
    const int ig   = bx >> 1;         // 0..3
    const int tid  = threadIdx.x;
    const int lane = tid & 31;
    const int il   = tid >> 5;        // warp id
    const int half = lane >> 4;       // which i within the warp
    const int lf   = lane & 15;       // f-quad index
    const int i    = ig * IPB + il * 2 + half;
    const int fb   = fh * FH + lf * 4;

    // tile loads: each half-tile = V*FH = 8192 floats = 2048 float4 (4/thread)
    {
        const float* e2g = g_e2 + (size_t)t * V * F + fh * FH;
        const float* whg = g_Wh + (size_t)t * V * F + fh * FH;
#pragma unroll
        for (int u = 0; u < 4; u++) {
            const int idx = tid + u * 512;     // 0..2047
            const int j = idx >> 4, c = idx & 15;
            ((float4*)e2s)[idx] = *(const float4*)(e2g + j * F + c * 4);
            ((float4*)whs)[idx] = *(const float4*)(whg + j * F + c * 4);
        }
        // adj rows for the 32 i's: 4096 floats = 1024 float4 (2/thread)
        ((float4*)adjs)[tid]       = ((const float4*)(adj + (size_t)ig * IPB * V))[tid];
        ((float4*)adjs)[tid + 512] = ((const float4*)(adj + (size_t)ig * IPB * V))[tid + 512];
    }

    const float4 e1v = *(const float4*)(g_e1 + ((size_t)t * V + i) * F + fb);
    __syncthreads();

    const float* adjrow = adjs + (il * 2 + half) * V;

    // Pass A: sum of exp + weighted numerator
    float4 s = {0.f, 0.f, 0.f, 0.f};
    float4 n = {0.f, 0.f, 0.f, 0.f};
#pragma unroll 4
    for (int j = 0; j < V; j++) {
        if (adjrow[j] > 0.0f) {
            const float4 e2v = *(const float4*)(e2s + j * FH + lf * 4);
            float v0 = e1v.x + e2v.x, v1 = e1v.y + e2v.y;
            float v2 = e1v.z + e2v.z, v3 = e1v.w + e2v.w;
            v0 = fmaxf(v0, LRELU_ALPHA * v0);
            v1 = fmaxf(v1, LRELU_ALPHA * v1);
            v2 = fmaxf(v2, LRELU_ALPHA * v2);
            v3 = fmaxf(v3, LRELU_ALPHA * v3);
            const float p0 = __expf(v0), p1 = __expf(v1);
            const float p2 = __expf(v2), p3 = __expf(v3);
            const float4 wv = *(const float4*)(whs + j * FH + lf * 4);
            s.x += p0; s.y += p1; s.z += p2; s.w += p3;
            n.x = fmaf(p0, wv.x, n.x);
            n.y = fmaf(p1, wv.y, n.y);
            n.z = fmaf(p2, wv.z, n.z);
            n.w = fmaf(p3, wv.w, n.w);
        }
    }

    const float r0 = 1.0f / s.x, r1 = 1.0f / s.y;
    const float r2 = 1.0f / s.z, r3 = 1.0f / s.w;

    // h_prime -> elu -> out (first tuple segment)
    {
        const float h0 = n.x * r0, h1 = n.y * r1;
        const float h2 = n.z * r2, h3 = n.w * r3;
        float4 o;
        o.x = (h0 > 0.0f) ? h0 : expm1f(h0);
        o.y = (h1 > 0.0f) ? h1 : expm1f(h1);
        o.z = (h2 > 0.0f) ? h2 : expm1f(h2);
        o.w = (h3 > 0.0f) ? h3 : expm1f(h3);
        *(float4*)(out + ((size_t)t * V + i) * F + fb) = o;
    }

    // Pass B: recompute exp for unmasked j; stream normalized attention
    float* ab = out + ATT_OFF + (((size_t)t * V + i) * V) * F + fb;
#pragma unroll 4
    for (int j = 0; j < V; j++) {
        float4 pv;
        if (adjrow[j] > 0.0f) {
            const float4 e2v = *(const float4*)(e2s + j * FH + lf * 4);
            float v0 = e1v.x + e2v.x, v1 = e1v.y + e2v.y;
            float v2 = e1v.z + e2v.z, v3 = e1v.w + e2v.w;
            v0 = fmaxf(v0, LRELU_ALPHA * v0);
            v1 = fmaxf(v1, LRELU_ALPHA * v1);
            v2 = fmaxf(v2, LRELU_ALPHA * v2);
            v3 = fmaxf(v3, LRELU_ALPHA * v3);
            pv.x = __expf(v0) * r0;
            pv.y = __expf(v1) * r1;
            pv.z = __expf(v2) * r2;
            pv.w = __expf(v3) * r3;
        } else {
            pv.x = 0.f; pv.y = 0.f; pv.z = 0.f; pv.w = 0.f;
        }
        __stcs((float4*)(ab + (size_t)j * F), pv);
    }
}

// ----------------------------------------------------------------------------
extern "C" void kernel_launch(void* const* d_in, const int* in_sizes, int n_in,
                              void* d_out, int out_size)
{
    const float* h   = (const float*)d_in[0];   // [2560,128]
    const float* adj = (const float*)d_in[1];   // [128,128,1]
    const float* W   = (const float*)d_in[2];   // [128,128]
    const float* a   = (const float*)d_in[3];   // [256,128]
    float* out = (float*)d_out;

    cudaFuncSetAttribute(attn_fused, cudaFuncAttributeMaxDynamicSharedMemorySize,
                         ATTN_SMEM_BYTES);

    gemm_fused<<<(NTIME * V) / MT, 256>>>(h, W, a);

    dim3 grid(8, NTIME);
    attn_fused<<<grid, 512, ATTN_SMEM_BYTES>>>(adj, out);
}

// round 4
// speedup vs baseline: 1.2341x; 1.2341x over previous
#include <cuda_runtime.h>
#include <cstdint>
#include <cstddef>

#define NTIME 20
#define V     128
#define F     128
#define LRELU_ALPHA 0.2f

#define OUT_HP_ELEMS   (NTIME * V * F)
#define ATT_OFF        OUT_HP_ELEMS

__device__ float g_Wh[NTIME * V * F];
__device__ float g_e1[NTIME * V * F];
__device__ float g_e2[NTIME * V * F];

// ----------------------------------------------------------------------------
// Kernel 1: fused  Wh = h @ W ;  e1 = Wh @ a[:128] ;  e2 = Wh @ a[128:]
// MT=16 rows/block, 256 threads (f = tid&127, half = tid>>7, 8 rows each).
// W/a values loaded once per thread and reused across 8 rows (halved LDG/output
// vs MT=8). k unrolled x4 with LDS.128 row fetches.
// ----------------------------------------------------------------------------
#define MT 16

__global__ void __launch_bounds__(256) gemm_fused(
    const float* __restrict__ h,
    const float* __restrict__ W,
    const float* __restrict__ a)
{
    __shared__ float hs[MT * F];
    __shared__ float whs[MT * F];

    const int tid  = threadIdx.x;
    const int f    = tid & 127;
    const int half = tid >> 7;
    const int m0   = blockIdx.x * MT;

    // h tile: 16*128 = 2048 floats = 512 float4 (2 per thread)
    {
        const float4* h4 = (const float4*)(h + (size_t)m0 * F);
        ((float4*)hs)[tid]       = h4[tid];
        ((float4*)hs)[tid + 256] = h4[tid + 256];
    }
    __syncthreads();

    float acc[8] = {0.f,0.f,0.f,0.f,0.f,0.f,0.f,0.f};

#pragma unroll 4
    for (int k4 = 0; k4 < F / 4; k4++) {
        float wv[4];
#pragma unroll
        for (int u = 0; u < 4; u++)
            wv[u] = __ldg(W + (k4 * 4 + u) * F + f);
#pragma unroll
        for (int r = 0; r < 8; r++) {
            const float4 hv = ((const float4*)(hs + (half * 8 + r) * F))[k4];
            acc[r] = fmaf(hv.x, wv[0], acc[r]);
            acc[r] = fmaf(hv.y, wv[1], acc[r]);
            acc[r] = fmaf(hv.z, wv[2], acc[r]);
            acc[r] = fmaf(hv.w, wv[3], acc[r]);
        }
    }

#pragma unroll
    for (int r = 0; r < 8; r++) {
        const int row = half * 8 + r;
        whs[row * F + f] = acc[r];
        g_Wh[(size_t)(m0 + row) * F + f] = acc[r];
    }
    __syncthreads();

    float ac1[8] = {0.f,0.f,0.f,0.f,0.f,0.f,0.f,0.f};
    float ac2[8] = {0.f,0.f,0.f,0.f,0.f,0.f,0.f,0.f};

#pragma unroll 2
    for (int k4 = 0; k4 < F / 4; k4++) {
        float a1v[4], a2v[4];
#pragma unroll
        for (int u = 0; u < 4; u++) {
            a1v[u] = __ldg(a + (k4 * 4 + u) * F + f);
            a2v[u] = __ldg(a + (F + k4 * 4 + u) * F + f);
        }
#pragma unroll
        for (int r = 0; r < 8; r++) {
            const float4 wv = ((const float4*)(whs + (half * 8 + r) * F))[k4];
            ac1[r] = fmaf(wv.x, a1v[0], ac1[r]);
            ac1[r] = fmaf(wv.y, a1v[1], ac1[r]);
            ac1[r] = fmaf(wv.z, a1v[2], ac1[r]);
            ac1[r] = fmaf(wv.w, a1v[3], ac1[r]);
            ac2[r] = fmaf(wv.x, a2v[0], ac2[r]);
            ac2[r] = fmaf(wv.y, a2v[1], ac2[r]);
            ac2[r] = fmaf(wv.z, a2v[2], ac2[r]);
            ac2[r] = fmaf(wv.w, a2v[3], ac2[r]);
        }
    }

#pragma unroll
    for (int r = 0; r < 8; r++) {
        const int row = half * 8 + r;
        g_e1[(size_t)(m0 + row) * F + f] = ac1[r];
        g_e2[(size_t)(m0 + row) * F + f] = ac2[r];
    }
}

// ----------------------------------------------------------------------------
// Kernel 2: fused leakyrelu + mask + softmax + weighted sum + elu + attn write.
//
// R2 layout (warp = one i -> warp-uniform adj branch; lane = 2 f's within a
// 64-wide f-half; grid = 16 x 20 = 320 blocks), upgraded:
//  - adjacency as a 128-bit register bitmask per warp (4x ballot) -> no adj
//    smem, branch test = SHF+ISETP, no LDS in the branch dependency chain
//  - smem = 64KB -> 3 CTAs/SM (48 warps), __launch_bounds__(512,3)
// ----------------------------------------------------------------------------
#define FH  64
#define IPB 16
#define ATTN_SMEM_BYTES ((V * FH * 2) * (int)sizeof(float))

__global__ void __launch_bounds__(512, 3) attn_fused(
    const float* __restrict__ adj,
    float* __restrict__ out)
{
    extern __shared__ float sm[];
    float* e2s = sm;                 // [V][FH]
    float* whs = sm + V * FH;        // [V][FH]

    const int t    = blockIdx.y;
    const int bx   = blockIdx.x;      // 0..15
    const int fh   = bx & 1;
    const int ig   = bx >> 1;         // 0..7
    const int tid  = threadIdx.x;
    const int lane = tid & 31;
    const int il   = tid >> 5;        // warp id = local i
    const int i    = ig * IPB + il;
    const int f2   = fh * FH + lane * 2;

    // adjacency bitmask for row i: 4 words x 32 bits (warp-uniform registers)
    uint32_t bits[4];
    {
        const float* arow = adj + (size_t)i * V;
#pragma unroll
        for (int w = 0; w < 4; w++)
            bits[w] = __ballot_sync(0xFFFFFFFFu, arow[w * 32 + lane] > 0.0f);
    }

    // cooperative tile loads: each half-tile = V*FH floats = 2048 float4
    {
        const float* e2g = g_e2 + (size_t)t * V * F + fh * FH;
        const float* whg = g_Wh + (size_t)t * V * F + fh * FH;
#pragma unroll
        for (int u = 0; u < 4; u++) {
            const int idx = tid + u * 512;     // 0..2047
            const int j = idx >> 4, c = idx & 15;
            ((float4*)e2s)[idx] = *(const float4*)(e2g + j * F + c * 4);
            ((float4*)whs)[idx] = *(const float4*)(whg + j * F + c * 4);
        }
    }

    const float2 e1v = *(const float2*)(g_e1 + ((size_t)t * V + i) * F + f2);
    __syncthreads();

    // Pass A: sum of exp + weighted numerator (warp-uniform bit test)
    float s0 = 0.0f, s1 = 0.0f, n0 = 0.0f, n1 = 0.0f;
#pragma unroll
    for (int w = 0; w < 4; w++) {
        const uint32_t bw = bits[w];
#pragma unroll 4
        for (int b = 0; b < 32; b++) {
            if (bw & (1u << b)) {
                const int j = w * 32 + b;
                const float2 e2v = *(const float2*)(e2s + j * FH + lane * 2);
                float v0 = e1v.x + e2v.x;
                float v1 = e1v.y + e2v.y;
                v0 = fmaxf(v0, LRELU_ALPHA * v0);
                v1 = fmaxf(v1, LRELU_ALPHA * v1);
                const float p0 = __expf(v0);
                const float p1 = __expf(v1);
                const float2 wv = *(const float2*)(whs + j * FH + lane * 2);
                s0 += p0;  s1 += p1;
                n0 = fmaf(p0, wv.x, n0);
                n1 = fmaf(p1, wv.y, n1);
            }
        }
    }

    const float r0 = 1.0f / s0;
    const float r1 = 1.0f / s1;

    // h_prime -> elu -> out (first tuple segment)
    {
        const float hp0 = n0 * r0;
        const float hp1 = n1 * r1;
        float2 o;
        o.x = (hp0 > 0.0f) ? hp0 : expm1f(hp0);
        o.y = (hp1 > 0.0f) ? hp1 : expm1f(hp1);
        *(float2*)(out + ((size_t)t * V + i) * F + f2) = o;
    }

    // Pass B: recompute exp only for unmasked j; stream normalized attention
    float* ab = out + ATT_OFF + (((size_t)t * V + i) * V) * F + f2;
#pragma unroll
    for (int w = 0; w < 4; w++) {
        const uint32_t bw = bits[w];
#pragma unroll 4
        for (int b = 0; b < 32; b++) {
            const int j = w * 32 + b;
            float2 pv;
            if (bw & (1u << b)) {
                const float2 e2v = *(const float2*)(e2s + j * FH + lane * 2);
                float v0 = e1v.x + e2v.x;
                float v1 = e1v.y + e2v.y;
                v0 = fmaxf(v0, LRELU_ALPHA * v0);
                v1 = fmaxf(v1, LRELU_ALPHA * v1);
                pv.x = __expf(v0) * r0;
                pv.y = __expf(v1) * r1;
            } else {
                pv.x = 0.0f; pv.y = 0.0f;
            }
            __stcs((float2*)(ab + (size_t)j * F), pv);
        }
    }
}

// ----------------------------------------------------------------------------
extern "C" void kernel_launch(void* const* d_in, const int* in_sizes, int n_in,
                              void* d_out, int out_size)
{
    const float* h   = (const float*)d_in[0];   // [2560,128]
    const float* adj = (const float*)d_in[1];   // [128,128,1]
    const float* W   = (const float*)d_in[2];   // [128,128]
    const float* a   = (const float*)d_in[3];   // [256,128]
    float* out = (float*)d_out;

    cudaFuncSetAttribute(attn_fused, cudaFuncAttributeMaxDynamicSharedMemorySize,
                         ATTN_SMEM_BYTES);

    gemm_fused<<<(NTIME * V) / MT, 256>>>(h, W, a);

    dim3 grid(16, NTIME);
    attn_fused<<<grid, 512, ATTN_SMEM_BYTES>>>(adj, out);
}